// round 16
// baseline (speedup 1.0000x reference)
#include <cuda_runtime.h>
#include <math.h>

// ---------------- problem constants ----------------
#define NB   256
#define TT   50
#define QD   8
#define HD   100
#define NS   (NB*TT)          // 12800
#define SDEC 4                // samples per decoder block
#define NDB  (NS/SDEC)        // 3200 decoder blocks
#define DT_C 0.1f
#define EPS_C 1e-5f

// ---------------- d_out layout (concat of tuple) ----------------
#define OFF_XREC 0
#define OFF_M    10035200
#define OFF_V    10037248
#define OFF_ZT   10039296
#define OFF_LH   10141696
#define OFF_KL   10141697

// ---------------- packed f32x2 helpers ----------------
typedef unsigned long long ull;
__device__ __forceinline__ ull pk2(float x, float y) {
    ull r; asm("mov.b64 %0,{%1,%2};" : "=l"(r) : "f"(x), "f"(y)); return r;
}
__device__ __forceinline__ void up2(ull v, float& x, float& y) {
    asm("mov.b64 {%0,%1},%2;" : "=f"(x), "=f"(y) : "l"(v));
}
__device__ __forceinline__ ull fma2(ull a, ull b, ull c) {
    ull d; asm("fma.rn.f32x2 %0,%1,%2,%3;" : "=l"(d) : "l"(a), "l"(b), "l"(c));
    return d;
}
__device__ __forceinline__ ull bcast2(float w) { return pk2(w, w); }

// ---------------- device scratch ----------------
__device__ float g_klb[NB * QD];
__device__ float g_lh[NDB];
__device__ float g_Wc[784 * 8];   // composed (convT1 o fc3) weight
__device__ float g_bc[784];       // composed bias
__device__ int   g_cnt;           // dec completion counter (zero-init)

// ============================================================
// Prep: compose fc3 + convT1 into Wc [784x8], bc [784]
// ============================================================
__global__ void __launch_bounds__(112)
prep_kernel(const float* __restrict__ fc3_w, const float* __restrict__ fc3_b,
            const float* __restrict__ w1, const float* __restrict__ b1) {
    int o = blockIdx.x * 112 + threadIdx.x;   // 7 blocks x 112 = 784
    if (o >= 784) return;
    int oc = o / 49, rem = o % 49, oy = rem / 7, ox = rem % 7;
    float acc[8];
#pragma unroll
    for (int j = 0; j < 8; j++) acc[j] = 0.f;
    float accb = 0.f;
    for (int ic = 0; ic < 32; ic++) {
#pragma unroll
        for (int iy = 0; iy < 4; iy++) {
            int ky = 2 * iy + 2 - oy;
            if (ky >= 0 && ky <= 4) {
#pragma unroll
                for (int ix = 0; ix < 4; ix++) {
                    int kx = 2 * ix + 2 - ox;
                    if (kx >= 0 && kx <= 4) {
                        float wv = __ldg(&w1[((oc * 32 + ic) * 5 + ky) * 5 + kx]);
                        int i = ic * 16 + iy * 4 + ix;
                        const float4* f = (const float4*)(fc3_w + i * 8);
                        float4 fa = __ldg(&f[0]), fb = __ldg(&f[1]);
                        acc[0] += wv * fa.x; acc[1] += wv * fa.y;
                        acc[2] += wv * fa.z; acc[3] += wv * fa.w;
                        acc[4] += wv * fb.x; acc[5] += wv * fb.y;
                        acc[6] += wv * fb.z; acc[7] += wv * fb.w;
                        accb += wv * __ldg(&fc3_b[i]);
                    }
                }
            }
        }
    }
#pragma unroll
    for (int j = 0; j < 8; j++) g_Wc[o * 8 + j] = acc[j];
    g_bc[o] = accb + __ldg(&b1[oc]);
}

// ============================================================
// Fused encoder: 2 samples per block, 256 threads (R13 version)
// Block 0 additionally resets the dec completion counter.
// ============================================================
__global__ void __launch_bounds__(256)
enc_kernel(const float* __restrict__ X,
           const float* __restrict__ w1, const float* __restrict__ b1,
           const float* __restrict__ w2, const float* __restrict__ b2,
           const float* __restrict__ w3, const float* __restrict__ b3,
           const float* __restrict__ fc1_w, const float* __restrict__ fc1_b,
           const float* __restrict__ fc2_w, const float* __restrict__ fc2_b,
           const float* __restrict__ eps_z, float* __restrict__ dout) {
    __shared__ float xin[2][784];
    __shared__ float w1s[200];
    __shared__ float h1[2][1568];
    __shared__ float w2s[3200];
    __shared__ float h2[2][784];
    __shared__ float h3[2][512];
    __shared__ float dots[2][16];

    int t  = threadIdx.x;
    int h  = t >> 7;
    int tl = t & 127;
    int n  = 2 * blockIdx.x + h;

    if (blockIdx.x == 0 && t == 0) g_cnt = 0;

    const float* xf = X + (size_t)n * (TT * 784);
    for (int i = tl; i < 784; i += 128) xin[h][i] = xf[i];
    for (int i = t; i < 200; i += 256) w1s[i] = w1[i];
    for (int i = t; i < 3200; i += 256) w2s[i] = w2[i];
    __syncthreads();

    if (tl < 112) {                          // conv1: 1->8, 28->14
        int oc = tl / 14, oy = tl % 14;
        float acc[14];
        float bb = __ldg(&b1[oc]);
#pragma unroll
        for (int o = 0; o < 14; o++) acc[o] = bb;
#pragma unroll
        for (int ky = 0; ky < 5; ky++) {
            int iy = 2 * oy + ky - 2;
            if (iy >= 0 && iy < 28) {
                const float* xr = xin[h] + iy * 28;
                const float* wr = w1s + (oc * 5 + ky) * 5;
#pragma unroll
                for (int kx = 0; kx < 5; kx++) {
                    float wv = wr[kx];
#pragma unroll
                    for (int ox = 0; ox < 14; ox++) {
                        int ix = 2 * ox + kx - 2;
                        if (ix >= 0 && ix < 28) acc[ox] += xr[ix] * wv;
                    }
                }
            }
        }
#pragma unroll
        for (int ox = 0; ox < 14; ox++)
            h1[h][(oc * 14 + oy) * 14 + ox] = fmaxf(acc[ox], 0.f);
    }
    __syncthreads();

    if (tl < 112) {                          // conv2: 8->16, 14->7
        int oc = tl / 7, oy = tl % 7;
        float acc[7];
        float bb = __ldg(&b2[oc]);
#pragma unroll
        for (int o = 0; o < 7; o++) acc[o] = bb;
        for (int ic = 0; ic < 8; ic++) {
#pragma unroll
            for (int ky = 0; ky < 5; ky++) {
                int iy = 2 * oy + ky - 2;
                if (iy >= 0 && iy < 14) {
                    const float* xr = h1[h] + (ic * 14 + iy) * 14;
                    const float* wr = w2s + ((oc * 8 + ic) * 5 + ky) * 5;
#pragma unroll
                    for (int kx = 0; kx < 5; kx++) {
                        float wv = wr[kx];
#pragma unroll
                        for (int ox = 0; ox < 7; ox++) {
                            int ix = 2 * ox + kx - 2;
                            if (ix >= 0 && ix < 14) acc[ox] += xr[ix] * wv;
                        }
                    }
                }
            }
        }
#pragma unroll
        for (int ox = 0; ox < 7; ox++)
            h2[h][(oc * 7 + oy) * 7 + ox] = fmaxf(acc[ox], 0.f);
    }
    __syncthreads();

    {                                        // conv3: 16->32, 7->4
        int oc = tl >> 2, oy = tl & 3;
        float acc[4];
        float bb = __ldg(&b3[oc]);
#pragma unroll
        for (int o = 0; o < 4; o++) acc[o] = bb;
        for (int ic = 0; ic < 16; ic++) {
#pragma unroll
            for (int ky = 0; ky < 5; ky++) {
                int iy = 2 * oy + ky - 2;
                if (iy >= 0 && iy < 7) {
                    const float* xr = h2[h] + (ic * 7 + iy) * 7;
                    const float* wr = w3 + ((oc * 16 + ic) * 5 + ky) * 5;
                    float wv[5];
#pragma unroll
                    for (int k = 0; k < 5; k++) wv[k] = __ldg(&wr[k]);
#pragma unroll
                    for (int kx = 0; kx < 5; kx++) {
#pragma unroll
                        for (int ox = 0; ox < 4; ox++) {
                            int ix = 2 * ox + kx - 2;
                            if (ix >= 0 && ix < 7) acc[ox] += xr[ix] * wv[kx];
                        }
                    }
                }
            }
        }
#pragma unroll
        for (int ox = 0; ox < 4; ox++)
            h3[h][oc * 16 + oy * 4 + ox] = fmaxf(acc[ox], 0.f);
    }
    __syncthreads();

    {                                        // fc1/fc2
        int warp = tl >> 5, lane = tl & 31;
        for (int d = warp * 4; d < warp * 4 + 4; d++) {
            const float* W = (d < 8) ? (fc1_w + d * 512) : (fc2_w + (d - 8) * 512);
            float p = 0.f;
            for (int i = lane; i < 512; i += 32) p += h3[h][i] * __ldg(&W[i]);
#pragma unroll
            for (int off = 16; off; off >>= 1)
                p += __shfl_xor_sync(0xffffffffu, p, off);
            if (lane == 0) dots[h][d] = p;
        }
    }
    __syncthreads();
    if (tl < 8) {
        float m  = dots[h][tl] + fc1_b[tl];
        float lv = dots[h][8 + tl] + fc2_b[tl];
        float v  = (lv > 15.f) ? lv : log1pf(expf(lv));
        float ez = eps_z[n * 8 + tl];
        float z0 = m + ez * v;
        dout[OFF_M + n * 8 + tl] = m;
        dout[OFF_V + n * 8 + tl] = v;
        dout[OFF_ZT + (size_t)(n * TT) * 8 + tl] = z0;
        g_klb[n * 8 + tl] = -logf(v) + 0.5f * (v * v + m * m) - 0.5f;
    }
}

// ============================================================
// RK4 ODE: 2 samples/block, W2 in registers (365us version)
// ============================================================
__global__ void __launch_bounds__(256, 1)
ode_kernel(const float* __restrict__ f_w1, const float* __restrict__ f_b1,
           const float* __restrict__ f_w2, const float* __restrict__ f_b2,
           const float* __restrict__ f_w3, const float* __restrict__ f_b3,
           float* __restrict__ dout) {
    __shared__ float w1s[800], b1s[100], b2s[100], w3s[800], b3s[8];
    __shared__ float2 a1p[100], a2p[100], zp[8], zinp[8], kp[4][8];

    int bidx = blockIdx.x;
    int t = threadIdx.x;
    int n0 = 2 * bidx, n1 = 2 * bidx + 1;

    for (int i = t; i < 800; i += 256) { w1s[i] = f_w1[i]; w3s[i] = f_w3[i]; }
    for (int i = t; i < 100; i += 256) { b1s[i] = f_b1[i]; b2s[i] = f_b2[i]; }
    if (t < 8) b3s[t] = f_b3[t];

    int h2i  = (t >> 1) < 100 ? (t >> 1) : 99;
    int half = t & 1;
    float w2r[50];
    {
        const float* src = f_w2 + h2i * 100 + half * 50;
#pragma unroll
        for (int i = 0; i < 50; i++) w2r[i] = src[i];
    }

    if (t < 8) {
        float a = dout[OFF_ZT + (size_t)(n0 * TT) * 8 + t];
        float bv = dout[OFF_ZT + (size_t)(n1 * TT) * 8 + t];
        zp[t] = make_float2(a, bv);
        zinp[t] = zp[t];
    }
    __syncthreads();

    const float HDT = 0.05f;
    const float C6  = (float)(0.1 / 6.0);

    auto feval = [&](int e, int step) {
        if (t < 100) {
            float ax = b1s[t], ay = b1s[t];
#pragma unroll
            for (int j = 0; j < 8; j++) {
                float wv = w1s[t * 8 + j];
                float2 z = zinp[j];
                ax += wv * z.x; ay += wv * z.y;
            }
            a1p[t] = make_float2(fmaxf(ax, 0.f), fmaxf(ay, 0.f));
        }
        __syncthreads();
        {
            float px0 = 0.f, px1 = 0.f, py0 = 0.f, py1 = 0.f;
            const float2* a = a1p + half * 50;
#pragma unroll
            for (int i = 0; i < 25; i++) {
                float2 v = a[i];
                px0 += w2r[i] * v.x; py0 += w2r[i] * v.y;
            }
#pragma unroll
            for (int i = 25; i < 50; i++) {
                float2 v = a[i];
                px1 += w2r[i] * v.x; py1 += w2r[i] * v.y;
            }
            float px = px0 + px1, py = py0 + py1;
            px += __shfl_xor_sync(0xffffffffu, px, 1);
            py += __shfl_xor_sync(0xffffffffu, py, 1);
            if (half == 0 && t < 200) {
                float bb = b2s[h2i];
                a2p[h2i] = make_float2(fmaxf(px + bb, 0.f), fmaxf(py + bb, 0.f));
            }
        }
        __syncthreads();
        if (t < 64) {
            int q = t >> 3, part = t & 7;
            float px = 0.f, py = 0.f;
            for (int h = part; h < 100; h += 8) {
                float wv = w3s[q * 100 + h];
                float2 v = a2p[h];
                px += wv * v.x; py += wv * v.y;
            }
#pragma unroll
            for (int off = 1; off < 8; off <<= 1) {
                px += __shfl_xor_sync(0xffffffffu, px, off);
                py += __shfl_xor_sync(0xffffffffu, py, off);
            }
            if (part == 0) {
                float2 k = make_float2(px + b3s[q], py + b3s[q]);
                kp[e][q] = k;
                float2 z = zp[q];
                if (e == 0 || e == 1) {
                    zinp[q] = make_float2(z.x + HDT * k.x, z.y + HDT * k.y);
                } else if (e == 2) {
                    zinp[q] = make_float2(z.x + DT_C * k.x, z.y + DT_C * k.y);
                } else {
                    float2 k1 = kp[0][q], k2 = kp[1][q], k3 = kp[2][q];
                    z.x += C6 * (k1.x + 2.f * k2.x + 2.f * k3.x + k.x);
                    z.y += C6 * (k1.y + 2.f * k2.y + 2.f * k3.y + k.y);
                    zp[q] = z; zinp[q] = z;
                    dout[OFF_ZT + (size_t)(n0 * TT + step + 1) * 8 + q] = z.x;
                    dout[OFF_ZT + (size_t)(n1 * TT + step + 1) * 8 + q] = z.y;
                }
            }
        }
        __syncthreads();
    };

    for (int step = 0; step < TT - 1; step++) {
        feval(0, step);
        feval(1, step);
        feval(2, step);
        feval(3, step);
    }
}

// ============================================================
// Fused decoder, SDEC=4, 128 threads, f32x2 packed (R13 hot
// loops). Last finished block performs the final reductions.
// ============================================================
__global__ void __launch_bounds__(128)
dec_kernel(const float* __restrict__ X,
           const float* __restrict__ w2, const float* __restrict__ b2,
           const float* __restrict__ w3, const float* __restrict__ b3,
           float* __restrict__ dout) {
    __shared__ __align__(16) float stv[8 * 4];   // z, sample-minor
    __shared__ __align__(16) float y1v[784 * 4]; // 16x7x7 [pix][s]
    __shared__ __align__(16) float y2v[1568 * 4];// 8x14x14 [pix][s]
    __shared__ float w3s[200];
    __shared__ float red[4];
    __shared__ int lastFlag;

    int s0 = blockIdx.x * SDEC;
    int t  = threadIdx.x;

    if (t < SDEC * 8) {
        int s = t >> 3, j = t & 7;
        stv[j * 4 + s] = dout[OFF_ZT + (size_t)(s0 + s) * 8 + j];
    }
    for (int i = t; i < 200; i += 128) w3s[i] = w3[i];
    __syncthreads();

    // ---- stage1: y1 = relu(Wc @ z + bc), 784 outputs ----
    {
        ull zlo[8], zhi[8];
#pragma unroll
        for (int j = 0; j < 8; j++) {
            zlo[j] = *(const ull*)&stv[j * 4];
            zhi[j] = *(const ull*)&stv[j * 4 + 2];
        }
        if (t < 112) {
            int oc = t / 7, oy = t % 7;
#pragma unroll
            for (int ox = 0; ox < 7; ox++) {
                int o = (oc * 7 + oy) * 7 + ox;
                const float4* wr = (const float4*)(g_Wc + o * 8);
                float4 wa = __ldg(&wr[0]), wb = __ldg(&wr[1]);
                float bb = __ldg(&g_bc[o]);
                ull a0 = pk2(bb, bb), a1 = a0;
                float wj[8] = {wa.x, wa.y, wa.z, wa.w, wb.x, wb.y, wb.z, wb.w};
#pragma unroll
                for (int j = 0; j < 8; j++) {
                    ull w2x = bcast2(wj[j]);
                    a0 = fma2(zlo[j], w2x, a0);
                    a1 = fma2(zhi[j], w2x, a1);
                }
                float a, b, c, d;
                up2(a0, a, b); up2(a1, c, d);
                *(float4*)&y1v[o * 4] = make_float4(fmaxf(a, 0.f), fmaxf(b, 0.f),
                                                    fmaxf(c, 0.f), fmaxf(d, 0.f));
            }
        }
    }
    __syncthreads();

    // ---- convT2: 16x7x7 -> 8x14x14, relu; warps 0-1 even oy, 2-3 odd ----
    {
        int oc = -1, oy = 0;
        if (t < 64)  { int oyE = t >> 3; if (oyE < 7) { oc = t & 7; oy = 2 * oyE; } }
        else         { int idx = t - 64; int oyO = idx >> 3; if (oyO < 7) { oc = idx & 7; oy = 2 * oyO + 1; } }
        if (oc >= 0) {
            float bb = __ldg(&b2[oc]);
            ull bb2 = pk2(bb, bb);
            ull acc0[14], acc1[14];
#pragma unroll
            for (int o = 0; o < 14; o++) { acc0[o] = bb2; acc1[o] = bb2; }

            auto body = [&](int ic, int iy, int ky) {
                const float* wr = w2 + ((oc * 16 + ic) * 5 + ky) * 5;
                ull wv2[5];
#pragma unroll
                for (int k = 0; k < 5; k++) wv2[k] = bcast2(__ldg(&wr[k]));
                ull lo[7], hi[7];
#pragma unroll
                for (int x = 0; x < 7; x++) {
                    ulonglong2 v = *(const ulonglong2*)&y1v[((ic * 7 + iy) * 7 + x) * 4];
                    lo[x] = v.x; hi[x] = v.y;
                }
#pragma unroll
                for (int ox = 0; ox < 14; ox++) {
#pragma unroll
                    for (int ix = 0; ix < 7; ix++) {
                        int kx = 2 * ix + 2 - ox;          // compile-time
                        if (kx >= 0 && kx <= 4) {
                            acc0[ox] = fma2(lo[ix], wv2[kx], acc0[ox]);
                            acc1[ox] = fma2(hi[ix], wv2[kx], acc1[ox]);
                        }
                    }
                }
            };

            if (t < 64) {
                int oyE = oy >> 1;
#pragma unroll
                for (int d = -1; d <= 1; d++) {
                    int iy = oyE + d;
                    if (iy >= 0 && iy <= 6) {
                        int ky = 2 * d + 2;
                        for (int ic = 0; ic < 16; ic++) body(ic, iy, ky);
                    }
                }
            } else {
                int oyO = (oy - 1) >> 1;
#pragma unroll
                for (int d = 0; d <= 1; d++) {
                    int iy = oyO + d;
                    if (iy <= 6) {
                        int ky = 2 * d + 1;
                        for (int ic = 0; ic < 16; ic++) body(ic, iy, ky);
                    }
                }
            }
#pragma unroll
            for (int ox = 0; ox < 14; ox++) {
                float a, b2f, c, d;
                up2(acc0[ox], a, b2f); up2(acc1[ox], c, d);
                int base = ((oc * 14 + oy) * 14 + ox) * 4;
                *(float4*)&y2v[base] = make_float4(fmaxf(a, 0.f), fmaxf(b2f, 0.f),
                                                   fmaxf(c, 0.f), fmaxf(d, 0.f));
            }
        }
    }
    __syncthreads();

    // ---- convT3: 8x14x14 -> 1x28x28 + sigmoid + lhood ----
    float lsum = 0.f;
    {
        int xh  = (t >= 64) ? 1 : 0;
        int idx = (t < 64) ? t : (t - 64);
        if (idx < 56) {
            int oy = idx >> 1, hseg = idx & 1;             // ox = 2*(7*hseg+j)+xh
            float bb = __ldg(&b3[0]);
            ull bb2 = pk2(bb, bb);
            ull acc0[7], acc1[7];
#pragma unroll
            for (int o = 0; o < 7; o++) { acc0[o] = bb2; acc1[o] = bb2; }
            int iyLo = (oy - 1) >> 1; if (iyLo < 0) iyLo = 0;
            int iyHi = (oy + 2) >> 1; if (iyHi > 13) iyHi = 13;
            int xb = 7 * hseg;
            for (int ic = 0; ic < 8; ic++) {
                for (int iy = iyLo; iy <= iyHi; iy++) {
                    int ky = 2 * iy + 2 - oy;              // in [0,4]
                    const float* wr = w3s + (ic * 5 + ky) * 5;
                    int rowb = (ic * 14 + iy) * 14;
                    if (xh == 0) {                          // kx in {0,2,4}
#pragma unroll
                        for (int e = 0; e < 3; e++) {
                            ull wv = bcast2(wr[2 * e]);
#pragma unroll
                            for (int j = 0; j < 7; j++) {
                                int ix = xb + j + e - 1;
                                if (ix >= 0 && ix <= 13) {
                                    ulonglong2 v = *(const ulonglong2*)&y2v[(rowb + ix) * 4];
                                    acc0[j] = fma2(v.x, wv, acc0[j]);
                                    acc1[j] = fma2(v.y, wv, acc1[j]);
                                }
                            }
                        }
                    } else {                                // kx in {1,3}
#pragma unroll
                        for (int e = 0; e < 2; e++) {
                            ull wv = bcast2(wr[2 * e + 1]);
#pragma unroll
                            for (int j = 0; j < 7; j++) {
                                int ix = xb + j + e;
                                if (ix <= 13) {
                                    ulonglong2 v = *(const ulonglong2*)&y2v[(rowb + ix) * 4];
                                    acc0[j] = fma2(v.x, wv, acc0[j]);
                                    acc1[j] = fma2(v.y, wv, acc1[j]);
                                }
                            }
                        }
                    }
                }
            }
            // sigmoid + Bernoulli log-lik per sample
#pragma unroll
            for (int j = 0; j < 7; j++) {
                int ox = 2 * (xb + j) + xh;
                float v[4];
                up2(acc0[j], v[0], v[1]); up2(acc1[j], v[2], v[3]);
#pragma unroll
                for (int s = 0; s < SDEC; s++) {
                    float e = __expf(-v[s]);
                    float y = __fdividef(1.f, 1.f + e);
                    size_t off = (size_t)(s0 + s) * 784 + oy * 28 + ox;
                    dout[OFF_XREC + off] = y;
                    float x = __ldg(&X[off]);
                    lsum += __logf(EPS_C + y) * x + __logf(EPS_C + 1.f - y) * (1.f - x);
                }
            }
        }
    }
#pragma unroll
    for (int off = 16; off; off >>= 1)
        lsum += __shfl_xor_sync(0xffffffffu, lsum, off);
    if ((t & 31) == 0) red[t >> 5] = lsum;
    __syncthreads();
    if (t == 0) {
        g_lh[blockIdx.x] = red[0] + red[1] + red[2] + red[3];
        __threadfence();
        int c = atomicAdd(&g_cnt, 1);
        lastFlag = (c == NDB - 1);
    }
    __syncthreads();

    // ---- last block: final deterministic reductions ----
    if (lastFlag) {
        __shared__ float sm[128];
        float a = 0.f;
        for (int i = t; i < NDB; i += 128) a += g_lh[i];   // fixed order
        sm[t] = a;
        __syncthreads();
        for (int off = 64; off; off >>= 1) {
            if (t < off) sm[t] += sm[t + off];
            __syncthreads();
        }
        if (t == 0) dout[OFF_LH] = sm[0] * (1.f / (float)NB);
        __syncthreads();
        float b = 0.f;
        for (int i = t; i < NB * QD; i += 128) b += g_klb[i];
        sm[t] = b;
        __syncthreads();
        for (int off = 64; off; off >>= 1) {
            if (t < off) sm[t] += sm[t + off];
            __syncthreads();
        }
        if (t == 0) dout[OFF_KL] = sm[0] * (1.f / (float)(NB * QD));
    }
}

// ============================================================
// launch: enc -> (fork: prep on s2) -> ode -> (join) -> dec
// Side stream enters capture via an event recorded on the
// origin stream AFTER a launch (R11-proven topology).
// ============================================================
extern "C" void kernel_launch(void* const* d_in, const int* in_sizes, int n_in,
                              void* d_out, int out_size) {
    const float* X      = (const float*)d_in[0];
    const float* eps_z  = (const float*)d_in[1];
    const float* enc_w1 = (const float*)d_in[2];
    const float* enc_b1 = (const float*)d_in[3];
    const float* enc_w2 = (const float*)d_in[4];
    const float* enc_b2 = (const float*)d_in[5];
    const float* enc_w3 = (const float*)d_in[6];
    const float* enc_b3 = (const float*)d_in[7];
    const float* fc1_w  = (const float*)d_in[8];
    const float* fc1_b  = (const float*)d_in[9];
    const float* fc2_w  = (const float*)d_in[10];
    const float* fc2_b  = (const float*)d_in[11];
    const float* f_w1   = (const float*)d_in[12];
    const float* f_b1   = (const float*)d_in[13];
    const float* f_w2   = (const float*)d_in[14];
    const float* f_b2   = (const float*)d_in[15];
    const float* f_w3   = (const float*)d_in[16];
    const float* f_b3   = (const float*)d_in[17];
    const float* fc3_w  = (const float*)d_in[18];
    const float* fc3_b  = (const float*)d_in[19];
    const float* dec_w1 = (const float*)d_in[20];
    const float* dec_b1 = (const float*)d_in[21];
    const float* dec_w2 = (const float*)d_in[22];
    const float* dec_b2 = (const float*)d_in[23];
    const float* dec_w3 = (const float*)d_in[24];
    const float* dec_b3 = (const float*)d_in[25];
    float* dout = (float*)d_out;

    cudaStream_t s2;
    cudaStreamCreateWithFlags(&s2, cudaStreamNonBlocking);
    cudaEvent_t evE, evP;
    cudaEventCreateWithFlags(&evE, cudaEventDisableTiming);
    cudaEventCreateWithFlags(&evP, cudaEventDisableTiming);

    enc_kernel<<<NB / 2, 256>>>(X, enc_w1, enc_b1, enc_w2, enc_b2,
                                enc_w3, enc_b3, fc1_w, fc1_b, fc2_w, fc2_b,
                                eps_z, dout);
    cudaEventRecord(evE, 0);

    // prep overlaps with the ODE on a side stream
    cudaStreamWaitEvent(s2, evE, 0);
    prep_kernel<<<7, 112, 0, s2>>>(fc3_w, fc3_b, dec_w1, dec_b1);
    cudaEventRecord(evP, s2);

    ode_kernel<<<NB / 2, 256>>>(f_w1, f_b1, f_w2, f_b2, f_w3, f_b3, dout);

    cudaStreamWaitEvent(0, evP, 0);
    dec_kernel<<<NDB, 128>>>(X, dec_w2, dec_b2, dec_w3, dec_b3, dout);
    // stream/event intentionally not destroyed: kernel_launch runs once for
    // correctness and once for graph capture.
}

// round 17
// speedup vs baseline: 1.6181x; 1.6181x over previous
#include <cuda_runtime.h>
#include <math.h>

// ---------------- problem constants ----------------
#define NB   256
#define TT   50
#define QD   8
#define HD   100
#define NS   (NB*TT)          // 12800
#define SDEC 4                // samples per decoder block
#define NDB  (NS/SDEC)        // 3200 decoder blocks
#define DT_C 0.1f
#define EPS_C 1e-5f

// ---------------- d_out layout (concat of tuple) ----------------
#define OFF_XREC 0
#define OFF_M    10035200
#define OFF_V    10037248
#define OFF_ZT   10039296
#define OFF_LH   10141696
#define OFF_KL   10141697

// ---------------- packed f32x2 helpers ----------------
typedef unsigned long long ull;
__device__ __forceinline__ ull pk2(float x, float y) {
    ull r; asm("mov.b64 %0,{%1,%2};" : "=l"(r) : "f"(x), "f"(y)); return r;
}
__device__ __forceinline__ void up2(ull v, float& x, float& y) {
    asm("mov.b64 {%0,%1},%2;" : "=f"(x), "=f"(y) : "l"(v));
}
__device__ __forceinline__ ull fma2(ull a, ull b, ull c) {
    ull d; asm("fma.rn.f32x2 %0,%1,%2,%3;" : "=l"(d) : "l"(a), "l"(b), "l"(c));
    return d;
}
__device__ __forceinline__ ull bcast2(float w) { return pk2(w, w); }

// ---------------- device scratch ----------------
__device__ float g_klb[NB * QD];
__device__ float g_lh[NDB];
__device__ float g_Wc[784 * 8];   // composed (convT1 o fc3) weight
__device__ float g_bc[784];       // composed bias

// ============================================================
// Prep: compose fc3 + convT1 into Wc [784x8], bc [784]
// ============================================================
__global__ void __launch_bounds__(112)
prep_kernel(const float* __restrict__ fc3_w, const float* __restrict__ fc3_b,
            const float* __restrict__ w1, const float* __restrict__ b1) {
    int o = blockIdx.x * 112 + threadIdx.x;   // 7 blocks x 112 = 784
    if (o >= 784) return;
    int oc = o / 49, rem = o % 49, oy = rem / 7, ox = rem % 7;
    float acc[8];
#pragma unroll
    for (int j = 0; j < 8; j++) acc[j] = 0.f;
    float accb = 0.f;
    for (int ic = 0; ic < 32; ic++) {
#pragma unroll
        for (int iy = 0; iy < 4; iy++) {
            int ky = 2 * iy + 2 - oy;
            if (ky >= 0 && ky <= 4) {
#pragma unroll
                for (int ix = 0; ix < 4; ix++) {
                    int kx = 2 * ix + 2 - ox;
                    if (kx >= 0 && kx <= 4) {
                        float wv = __ldg(&w1[((oc * 32 + ic) * 5 + ky) * 5 + kx]);
                        int i = ic * 16 + iy * 4 + ix;
                        const float4* f = (const float4*)(fc3_w + i * 8);
                        float4 fa = __ldg(&f[0]), fb = __ldg(&f[1]);
                        acc[0] += wv * fa.x; acc[1] += wv * fa.y;
                        acc[2] += wv * fa.z; acc[3] += wv * fa.w;
                        acc[4] += wv * fb.x; acc[5] += wv * fb.y;
                        acc[6] += wv * fb.z; acc[7] += wv * fb.w;
                        accb += wv * __ldg(&fc3_b[i]);
                    }
                }
            }
        }
    }
#pragma unroll
    for (int j = 0; j < 8; j++) g_Wc[o * 8 + j] = acc[j];
    g_bc[o] = accb + __ldg(&b1[oc]);
}

// ============================================================
// Fused encoder: 2 samples per block, 256 threads (R13 version)
// ============================================================
__global__ void __launch_bounds__(256)
enc_kernel(const float* __restrict__ X,
           const float* __restrict__ w1, const float* __restrict__ b1,
           const float* __restrict__ w2, const float* __restrict__ b2,
           const float* __restrict__ w3, const float* __restrict__ b3,
           const float* __restrict__ fc1_w, const float* __restrict__ fc1_b,
           const float* __restrict__ fc2_w, const float* __restrict__ fc2_b,
           const float* __restrict__ eps_z, float* __restrict__ dout) {
    __shared__ float xin[2][784];
    __shared__ float w1s[200];
    __shared__ float h1[2][1568];
    __shared__ float w2s[3200];
    __shared__ float h2[2][784];
    __shared__ float h3[2][512];
    __shared__ float dots[2][16];

    int t  = threadIdx.x;
    int h  = t >> 7;
    int tl = t & 127;
    int n  = 2 * blockIdx.x + h;

    const float* xf = X + (size_t)n * (TT * 784);
    for (int i = tl; i < 784; i += 128) xin[h][i] = xf[i];
    for (int i = t; i < 200; i += 256) w1s[i] = w1[i];
    for (int i = t; i < 3200; i += 256) w2s[i] = w2[i];
    __syncthreads();

    if (tl < 112) {                          // conv1: 1->8, 28->14
        int oc = tl / 14, oy = tl % 14;
        float acc[14];
        float bb = __ldg(&b1[oc]);
#pragma unroll
        for (int o = 0; o < 14; o++) acc[o] = bb;
#pragma unroll
        for (int ky = 0; ky < 5; ky++) {
            int iy = 2 * oy + ky - 2;
            if (iy >= 0 && iy < 28) {
                const float* xr = xin[h] + iy * 28;
                const float* wr = w1s + (oc * 5 + ky) * 5;
#pragma unroll
                for (int kx = 0; kx < 5; kx++) {
                    float wv = wr[kx];
#pragma unroll
                    for (int ox = 0; ox < 14; ox++) {
                        int ix = 2 * ox + kx - 2;
                        if (ix >= 0 && ix < 28) acc[ox] += xr[ix] * wv;
                    }
                }
            }
        }
#pragma unroll
        for (int ox = 0; ox < 14; ox++)
            h1[h][(oc * 14 + oy) * 14 + ox] = fmaxf(acc[ox], 0.f);
    }
    __syncthreads();

    if (tl < 112) {                          // conv2: 8->16, 14->7
        int oc = tl / 7, oy = tl % 7;
        float acc[7];
        float bb = __ldg(&b2[oc]);
#pragma unroll
        for (int o = 0; o < 7; o++) acc[o] = bb;
        for (int ic = 0; ic < 8; ic++) {
#pragma unroll
            for (int ky = 0; ky < 5; ky++) {
                int iy = 2 * oy + ky - 2;
                if (iy >= 0 && iy < 14) {
                    const float* xr = h1[h] + (ic * 14 + iy) * 14;
                    const float* wr = w2s + ((oc * 8 + ic) * 5 + ky) * 5;
#pragma unroll
                    for (int kx = 0; kx < 5; kx++) {
                        float wv = wr[kx];
#pragma unroll
                        for (int ox = 0; ox < 7; ox++) {
                            int ix = 2 * ox + kx - 2;
                            if (ix >= 0 && ix < 14) acc[ox] += xr[ix] * wv;
                        }
                    }
                }
            }
        }
#pragma unroll
        for (int ox = 0; ox < 7; ox++)
            h2[h][(oc * 7 + oy) * 7 + ox] = fmaxf(acc[ox], 0.f);
    }
    __syncthreads();

    {                                        // conv3: 16->32, 7->4
        int oc = tl >> 2, oy = tl & 3;
        float acc[4];
        float bb = __ldg(&b3[oc]);
#pragma unroll
        for (int o = 0; o < 4; o++) acc[o] = bb;
        for (int ic = 0; ic < 16; ic++) {
#pragma unroll
            for (int ky = 0; ky < 5; ky++) {
                int iy = 2 * oy + ky - 2;
                if (iy >= 0 && iy < 7) {
                    const float* xr = h2[h] + (ic * 7 + iy) * 7;
                    const float* wr = w3 + ((oc * 16 + ic) * 5 + ky) * 5;
                    float wv[5];
#pragma unroll
                    for (int k = 0; k < 5; k++) wv[k] = __ldg(&wr[k]);
#pragma unroll
                    for (int kx = 0; kx < 5; kx++) {
#pragma unroll
                        for (int ox = 0; ox < 4; ox++) {
                            int ix = 2 * ox + kx - 2;
                            if (ix >= 0 && ix < 7) acc[ox] += xr[ix] * wv[kx];
                        }
                    }
                }
            }
        }
#pragma unroll
        for (int ox = 0; ox < 4; ox++)
            h3[h][oc * 16 + oy * 4 + ox] = fmaxf(acc[ox], 0.f);
    }
    __syncthreads();

    {                                        // fc1/fc2
        int warp = tl >> 5, lane = tl & 31;
        for (int d = warp * 4; d < warp * 4 + 4; d++) {
            const float* W = (d < 8) ? (fc1_w + d * 512) : (fc2_w + (d - 8) * 512);
            float p = 0.f;
            for (int i = lane; i < 512; i += 32) p += h3[h][i] * __ldg(&W[i]);
#pragma unroll
            for (int off = 16; off; off >>= 1)
                p += __shfl_xor_sync(0xffffffffu, p, off);
            if (lane == 0) dots[h][d] = p;
        }
    }
    __syncthreads();
    if (tl < 8) {
        float m  = dots[h][tl] + fc1_b[tl];
        float lv = dots[h][8 + tl] + fc2_b[tl];
        float v  = (lv > 15.f) ? lv : log1pf(expf(lv));
        float ez = eps_z[n * 8 + tl];
        float z0 = m + ez * v;
        dout[OFF_M + n * 8 + tl] = m;
        dout[OFF_V + n * 8 + tl] = v;
        dout[OFF_ZT + (size_t)(n * TT) * 8 + tl] = z0;
        g_klb[n * 8 + tl] = -logf(v) + 0.5f * (v * v + m * m) - 0.5f;
    }
}

// ============================================================
// RK4 ODE: 2 samples/block, W2 in registers (365us version)
// ============================================================
__global__ void __launch_bounds__(256, 1)
ode_kernel(const float* __restrict__ f_w1, const float* __restrict__ f_b1,
           const float* __restrict__ f_w2, const float* __restrict__ f_b2,
           const float* __restrict__ f_w3, const float* __restrict__ f_b3,
           float* __restrict__ dout) {
    __shared__ float w1s[800], b1s[100], b2s[100], w3s[800], b3s[8];
    __shared__ float2 a1p[100], a2p[100], zp[8], zinp[8], kp[4][8];

    int bidx = blockIdx.x;
    int t = threadIdx.x;
    int n0 = 2 * bidx, n1 = 2 * bidx + 1;

    for (int i = t; i < 800; i += 256) { w1s[i] = f_w1[i]; w3s[i] = f_w3[i]; }
    for (int i = t; i < 100; i += 256) { b1s[i] = f_b1[i]; b2s[i] = f_b2[i]; }
    if (t < 8) b3s[t] = f_b3[t];

    int h2i  = (t >> 1) < 100 ? (t >> 1) : 99;
    int half = t & 1;
    float w2r[50];
    {
        const float* src = f_w2 + h2i * 100 + half * 50;
#pragma unroll
        for (int i = 0; i < 50; i++) w2r[i] = src[i];
    }

    if (t < 8) {
        float a = dout[OFF_ZT + (size_t)(n0 * TT) * 8 + t];
        float bv = dout[OFF_ZT + (size_t)(n1 * TT) * 8 + t];
        zp[t] = make_float2(a, bv);
        zinp[t] = zp[t];
    }
    __syncthreads();

    const float HDT = 0.05f;
    const float C6  = (float)(0.1 / 6.0);

    auto feval = [&](int e, int step) {
        if (t < 100) {
            float ax = b1s[t], ay = b1s[t];
#pragma unroll
            for (int j = 0; j < 8; j++) {
                float wv = w1s[t * 8 + j];
                float2 z = zinp[j];
                ax += wv * z.x; ay += wv * z.y;
            }
            a1p[t] = make_float2(fmaxf(ax, 0.f), fmaxf(ay, 0.f));
        }
        __syncthreads();
        {
            float px0 = 0.f, px1 = 0.f, py0 = 0.f, py1 = 0.f;
            const float2* a = a1p + half * 50;
#pragma unroll
            for (int i = 0; i < 25; i++) {
                float2 v = a[i];
                px0 += w2r[i] * v.x; py0 += w2r[i] * v.y;
            }
#pragma unroll
            for (int i = 25; i < 50; i++) {
                float2 v = a[i];
                px1 += w2r[i] * v.x; py1 += w2r[i] * v.y;
            }
            float px = px0 + px1, py = py0 + py1;
            px += __shfl_xor_sync(0xffffffffu, px, 1);
            py += __shfl_xor_sync(0xffffffffu, py, 1);
            if (half == 0 && t < 200) {
                float bb = b2s[h2i];
                a2p[h2i] = make_float2(fmaxf(px + bb, 0.f), fmaxf(py + bb, 0.f));
            }
        }
        __syncthreads();
        if (t < 64) {
            int q = t >> 3, part = t & 7;
            float px = 0.f, py = 0.f;
            for (int h = part; h < 100; h += 8) {
                float wv = w3s[q * 100 + h];
                float2 v = a2p[h];
                px += wv * v.x; py += wv * v.y;
            }
#pragma unroll
            for (int off = 1; off < 8; off <<= 1) {
                px += __shfl_xor_sync(0xffffffffu, px, off);
                py += __shfl_xor_sync(0xffffffffu, py, off);
            }
            if (part == 0) {
                float2 k = make_float2(px + b3s[q], py + b3s[q]);
                kp[e][q] = k;
                float2 z = zp[q];
                if (e == 0 || e == 1) {
                    zinp[q] = make_float2(z.x + HDT * k.x, z.y + HDT * k.y);
                } else if (e == 2) {
                    zinp[q] = make_float2(z.x + DT_C * k.x, z.y + DT_C * k.y);
                } else {
                    float2 k1 = kp[0][q], k2 = kp[1][q], k3 = kp[2][q];
                    z.x += C6 * (k1.x + 2.f * k2.x + 2.f * k3.x + k.x);
                    z.y += C6 * (k1.y + 2.f * k2.y + 2.f * k3.y + k.y);
                    zp[q] = z; zinp[q] = z;
                    dout[OFF_ZT + (size_t)(n0 * TT + step + 1) * 8 + q] = z.x;
                    dout[OFF_ZT + (size_t)(n1 * TT + step + 1) * 8 + q] = z.y;
                }
            }
        }
        __syncthreads();
    };

    for (int step = 0; step < TT - 1; step++) {
        feval(0, step);
        feval(1, step);
        feval(2, step);
        feval(3, step);
    }
}

// ============================================================
// Fused decoder, SDEC=4, 128 threads, f32x2 packed (365us
// version — no epilogue fold, regs stay at 96)
// ============================================================
__global__ void __launch_bounds__(128)
dec_kernel(const float* __restrict__ X,
           const float* __restrict__ w2, const float* __restrict__ b2,
           const float* __restrict__ w3, const float* __restrict__ b3,
           float* __restrict__ dout) {
    __shared__ __align__(16) float stv[8 * 4];   // z, sample-minor
    __shared__ __align__(16) float y1v[784 * 4]; // 16x7x7 [pix][s]
    __shared__ __align__(16) float y2v[1568 * 4];// 8x14x14 [pix][s]
    __shared__ float w3s[200];
    __shared__ float red[4];

    int s0 = blockIdx.x * SDEC;
    int t  = threadIdx.x;

    if (t < SDEC * 8) {
        int s = t >> 3, j = t & 7;
        stv[j * 4 + s] = dout[OFF_ZT + (size_t)(s0 + s) * 8 + j];
    }
    for (int i = t; i < 200; i += 128) w3s[i] = w3[i];
    __syncthreads();

    // ---- stage1: y1 = relu(Wc @ z + bc), 784 outputs ----
    {
        ull zlo[8], zhi[8];
#pragma unroll
        for (int j = 0; j < 8; j++) {
            zlo[j] = *(const ull*)&stv[j * 4];
            zhi[j] = *(const ull*)&stv[j * 4 + 2];
        }
        if (t < 112) {
            int oc = t / 7, oy = t % 7;
#pragma unroll
            for (int ox = 0; ox < 7; ox++) {
                int o = (oc * 7 + oy) * 7 + ox;
                const float4* wr = (const float4*)(g_Wc + o * 8);
                float4 wa = __ldg(&wr[0]), wb = __ldg(&wr[1]);
                float bb = __ldg(&g_bc[o]);
                ull a0 = pk2(bb, bb), a1 = a0;
                float wj[8] = {wa.x, wa.y, wa.z, wa.w, wb.x, wb.y, wb.z, wb.w};
#pragma unroll
                for (int j = 0; j < 8; j++) {
                    ull w2x = bcast2(wj[j]);
                    a0 = fma2(zlo[j], w2x, a0);
                    a1 = fma2(zhi[j], w2x, a1);
                }
                float a, b, c, d;
                up2(a0, a, b); up2(a1, c, d);
                *(float4*)&y1v[o * 4] = make_float4(fmaxf(a, 0.f), fmaxf(b, 0.f),
                                                    fmaxf(c, 0.f), fmaxf(d, 0.f));
            }
        }
    }
    __syncthreads();

    // ---- convT2: 16x7x7 -> 8x14x14, relu; warps 0-1 even oy, 2-3 odd ----
    {
        int oc = -1, oy = 0;
        if (t < 64)  { int oyE = t >> 3; if (oyE < 7) { oc = t & 7; oy = 2 * oyE; } }
        else         { int idx = t - 64; int oyO = idx >> 3; if (oyO < 7) { oc = idx & 7; oy = 2 * oyO + 1; } }
        if (oc >= 0) {
            float bb = __ldg(&b2[oc]);
            ull bb2 = pk2(bb, bb);
            ull acc0[14], acc1[14];
#pragma unroll
            for (int o = 0; o < 14; o++) { acc0[o] = bb2; acc1[o] = bb2; }

            auto body = [&](int ic, int iy, int ky) {
                const float* wr = w2 + ((oc * 16 + ic) * 5 + ky) * 5;
                ull wv2[5];
#pragma unroll
                for (int k = 0; k < 5; k++) wv2[k] = bcast2(__ldg(&wr[k]));
                ull lo[7], hi[7];
#pragma unroll
                for (int x = 0; x < 7; x++) {
                    ulonglong2 v = *(const ulonglong2*)&y1v[((ic * 7 + iy) * 7 + x) * 4];
                    lo[x] = v.x; hi[x] = v.y;
                }
#pragma unroll
                for (int ox = 0; ox < 14; ox++) {
#pragma unroll
                    for (int ix = 0; ix < 7; ix++) {
                        int kx = 2 * ix + 2 - ox;          // compile-time
                        if (kx >= 0 && kx <= 4) {
                            acc0[ox] = fma2(lo[ix], wv2[kx], acc0[ox]);
                            acc1[ox] = fma2(hi[ix], wv2[kx], acc1[ox]);
                        }
                    }
                }
            };

            if (t < 64) {
                int oyE = oy >> 1;
#pragma unroll
                for (int d = -1; d <= 1; d++) {
                    int iy = oyE + d;
                    if (iy >= 0 && iy <= 6) {
                        int ky = 2 * d + 2;
                        for (int ic = 0; ic < 16; ic++) body(ic, iy, ky);
                    }
                }
            } else {
                int oyO = (oy - 1) >> 1;
#pragma unroll
                for (int d = 0; d <= 1; d++) {
                    int iy = oyO + d;
                    if (iy <= 6) {
                        int ky = 2 * d + 1;
                        for (int ic = 0; ic < 16; ic++) body(ic, iy, ky);
                    }
                }
            }
#pragma unroll
            for (int ox = 0; ox < 14; ox++) {
                float a, b2f, c, d;
                up2(acc0[ox], a, b2f); up2(acc1[ox], c, d);
                int base = ((oc * 14 + oy) * 14 + ox) * 4;
                *(float4*)&y2v[base] = make_float4(fmaxf(a, 0.f), fmaxf(b2f, 0.f),
                                                   fmaxf(c, 0.f), fmaxf(d, 0.f));
            }
        }
    }
    __syncthreads();

    // ---- convT3: 8x14x14 -> 1x28x28 + sigmoid + lhood ----
    float lsum = 0.f;
    {
        int xh  = (t >= 64) ? 1 : 0;
        int idx = (t < 64) ? t : (t - 64);
        if (idx < 56) {
            int oy = idx >> 1, hseg = idx & 1;             // ox = 2*(7*hseg+j)+xh
            float bb = __ldg(&b3[0]);
            ull bb2 = pk2(bb, bb);
            ull acc0[7], acc1[7];
#pragma unroll
            for (int o = 0; o < 7; o++) { acc0[o] = bb2; acc1[o] = bb2; }
            int iyLo = (oy - 1) >> 1; if (iyLo < 0) iyLo = 0;
            int iyHi = (oy + 2) >> 1; if (iyHi > 13) iyHi = 13;
            int xb = 7 * hseg;
            for (int ic = 0; ic < 8; ic++) {
                for (int iy = iyLo; iy <= iyHi; iy++) {
                    int ky = 2 * iy + 2 - oy;              // in [0,4]
                    const float* wr = w3s + (ic * 5 + ky) * 5;
                    int rowb = (ic * 14 + iy) * 14;
                    if (xh == 0) {                          // kx in {0,2,4}
#pragma unroll
                        for (int e = 0; e < 3; e++) {
                            ull wv = bcast2(wr[2 * e]);
#pragma unroll
                            for (int j = 0; j < 7; j++) {
                                int ix = xb + j + e - 1;
                                if (ix >= 0 && ix <= 13) {
                                    ulonglong2 v = *(const ulonglong2*)&y2v[(rowb + ix) * 4];
                                    acc0[j] = fma2(v.x, wv, acc0[j]);
                                    acc1[j] = fma2(v.y, wv, acc1[j]);
                                }
                            }
                        }
                    } else {                                // kx in {1,3}
#pragma unroll
                        for (int e = 0; e < 2; e++) {
                            ull wv = bcast2(wr[2 * e + 1]);
#pragma unroll
                            for (int j = 0; j < 7; j++) {
                                int ix = xb + j + e;
                                if (ix <= 13) {
                                    ulonglong2 v = *(const ulonglong2*)&y2v[(rowb + ix) * 4];
                                    acc0[j] = fma2(v.x, wv, acc0[j]);
                                    acc1[j] = fma2(v.y, wv, acc1[j]);
                                }
                            }
                        }
                    }
                }
            }
            // sigmoid + Bernoulli log-lik per sample
#pragma unroll
            for (int j = 0; j < 7; j++) {
                int ox = 2 * (xb + j) + xh;
                float v[4];
                up2(acc0[j], v[0], v[1]); up2(acc1[j], v[2], v[3]);
#pragma unroll
                for (int s = 0; s < SDEC; s++) {
                    float e = __expf(-v[s]);
                    float y = __fdividef(1.f, 1.f + e);
                    size_t off = (size_t)(s0 + s) * 784 + oy * 28 + ox;
                    dout[OFF_XREC + off] = y;
                    float x = __ldg(&X[off]);
                    lsum += __logf(EPS_C + y) * x + __logf(EPS_C + 1.f - y) * (1.f - x);
                }
            }
        }
    }
#pragma unroll
    for (int off = 16; off; off >>= 1)
        lsum += __shfl_xor_sync(0xffffffffu, lsum, off);
    if ((t & 31) == 0) red[t >> 5] = lsum;
    __syncthreads();
    if (t == 0) g_lh[blockIdx.x] = red[0] + red[1] + red[2] + red[3];
}

// ============================================================
// Final deterministic reductions
// ============================================================
__global__ void __launch_bounds__(1024)
reduce_kernel(float* __restrict__ dout) {
    __shared__ float sm[1024];
    int t = threadIdx.x;
    float a = 0.f;
    for (int i = t * 4; i < NDB; i += 4096) {
        float4 v = *(const float4*)&g_lh[i];
        a += (v.x + v.y) + (v.z + v.w);
    }
    sm[t] = a;
    __syncthreads();
    for (int off = 512; off; off >>= 1) {
        if (t < off) sm[t] += sm[t + off];
        __syncthreads();
    }
    if (t == 0) dout[OFF_LH] = sm[0] * (1.f / (float)NB);
    __syncthreads();
    float b = 0.f;
    if (t < 512) {
        float4 v = *(const float4*)&g_klb[t * 4];
        b = (v.x + v.y) + (v.z + v.w);
    }
    sm[t] = b;
    __syncthreads();
    for (int off = 512; off; off >>= 1) {
        if (t < off) sm[t] += sm[t + off];
        __syncthreads();
    }
    if (t == 0) dout[OFF_KL] = sm[0] * (1.f / (float)(NB * QD));
}

// ============================================================
// launch: enc -> (fork: prep on s2, overlaps ode) -> join -> dec
// -> reduce.  Fork topology proven capture-safe in R16.
// ============================================================
extern "C" void kernel_launch(void* const* d_in, const int* in_sizes, int n_in,
                              void* d_out, int out_size) {
    const float* X      = (const float*)d_in[0];
    const float* eps_z  = (const float*)d_in[1];
    const float* enc_w1 = (const float*)d_in[2];
    const float* enc_b1 = (const float*)d_in[3];
    const float* enc_w2 = (const float*)d_in[4];
    const float* enc_b2 = (const float*)d_in[5];
    const float* enc_w3 = (const float*)d_in[6];
    const float* enc_b3 = (const float*)d_in[7];
    const float* fc1_w  = (const float*)d_in[8];
    const float* fc1_b  = (const float*)d_in[9];
    const float* fc2_w  = (const float*)d_in[10];
    const float* fc2_b  = (const float*)d_in[11];
    const float* f_w1   = (const float*)d_in[12];
    const float* f_b1   = (const float*)d_in[13];
    const float* f_w2   = (const float*)d_in[14];
    const float* f_b2   = (const float*)d_in[15];
    const float* f_w3   = (const float*)d_in[16];
    const float* f_b3   = (const float*)d_in[17];
    const float* fc3_w  = (const float*)d_in[18];
    const float* fc3_b  = (const float*)d_in[19];
    const float* dec_w1 = (const float*)d_in[20];
    const float* dec_b1 = (const float*)d_in[21];
    const float* dec_w2 = (const float*)d_in[22];
    const float* dec_b2 = (const float*)d_in[23];
    const float* dec_w3 = (const float*)d_in[24];
    const float* dec_b3 = (const float*)d_in[25];
    float* dout = (float*)d_out;

    cudaStream_t s2;
    cudaStreamCreateWithFlags(&s2, cudaStreamNonBlocking);
    cudaEvent_t evE, evP;
    cudaEventCreateWithFlags(&evE, cudaEventDisableTiming);
    cudaEventCreateWithFlags(&evP, cudaEventDisableTiming);

    enc_kernel<<<NB / 2, 256>>>(X, enc_w1, enc_b1, enc_w2, enc_b2,
                                enc_w3, enc_b3, fc1_w, fc1_b, fc2_w, fc2_b,
                                eps_z, dout);
    cudaEventRecord(evE, 0);

    // prep overlaps with the ODE on a side stream
    cudaStreamWaitEvent(s2, evE, 0);
    prep_kernel<<<7, 112, 0, s2>>>(fc3_w, fc3_b, dec_w1, dec_b1);
    cudaEventRecord(evP, s2);

    ode_kernel<<<NB / 2, 256>>>(f_w1, f_b1, f_w2, f_b2, f_w3, f_b3, dout);

    cudaStreamWaitEvent(0, evP, 0);
    dec_kernel<<<NDB, 128>>>(X, dec_w2, dec_b2, dec_w3, dec_b3, dout);
    reduce_kernel<<<1, 1024>>>(dout);
    // stream/event intentionally not destroyed: kernel_launch runs once for
    // correctness and once for graph capture.
}